// round 13
// baseline (speedup 1.0000x reference)
#include <cuda_runtime.h>
#include <cuda_fp16.h>
#include <cstdint>

#define Bsz 1024
#define Tt  128
#define Dd  64
#define Hh  256
#define MB  4            // batch rows per CTA
#define NT  256
#define GRID 256         // 2 CTAs per SM

typedef unsigned long long u64;

// ------------------- device scratch -------------------
__device__ float tdhT_g[Dd * Hh];        // td_h_W^T  [k][c]
__device__ float tdxT_g[Dd * Dd];        // td_x_W^T  [k][j]
__device__ float Gh_g[Bsz * Tt * Hh];    // gamma_h   [b*T+t][256]
__device__ float alpha_g[Bsz * Tt * Dd]; // alpha     [b*T+t][64]
__device__ __half WEHrk_g[Hh * 1024];    // lstmRK fp16
__device__ __half WEHk_g[2 * Dd * 1024]; // lstmK  fp16

__device__ __forceinline__ u64 dup2(float w) {
    u64 r; asm("mov.b64 %0, {%1,%1};" : "=l"(r) : "f"(w)); return r;
}
__device__ __forceinline__ void upk2(u64 v, float& lo, float& hi) {
    asm("mov.b64 {%0,%1}, %2;" : "=f"(lo), "=f"(hi) : "l"(v));
}
__device__ __forceinline__ u64 fma2(u64 a, u64 b, u64 c) {
    u64 d; asm("fma.rn.f32x2 %0, %1, %2, %3;" : "=l"(d) : "l"(a), "l"(b), "l"(c)); return d;
}
__device__ __forceinline__ float sigf(float x) {
    return __fdividef(1.f, 1.f + __expf(-x));
}
__device__ __forceinline__ float tanhfast(float x) {
    return __fdividef(2.f, 1.f + __expf(-2.f * x)) - 1.f;
}

// ============================ precompute kernels ============================

__global__ void transpose_kernel(const float* __restrict__ tdhW,
                                 const float* __restrict__ tdxW) {
    int idx = blockIdx.x * 256 + threadIdx.x;
    if (idx < Hh * Dd) {
        int c = idx >> 6, k = idx & 63;
        tdhT_g[k * Hh + c] = tdhW[idx];
    } else if (idx < Hh * Dd + Dd * Dd) {
        int e = idx - Hh * Dd;
        int j = e >> 6, k = e & 63;
        tdxT_g[k * Dd + j] = tdxW[e];
    }
}

__global__ void pack_h_kernel(const float* __restrict__ rk,
                              const float* __restrict__ kk) {
    int idx = blockIdx.x * 256 + threadIdx.x;
    if (idx < Hh * 1024)
        WEHrk_g[idx] = __float2half(rk[idx]);
    else if (idx < Hh * 1024 + 2 * Dd * 1024) {
        int e = idx - Hh * 1024;
        WEHk_g[e] = __float2half(kk[e]);
    }
}

// gamma_h AND (gamma_x -> alpha) for 8 rows/CTA (shares delta/mask loads)
__global__ void __launch_bounds__(256) pre_ga_kernel(
    const float* __restrict__ deltas, const float* __restrict__ masks,
    const float* __restrict__ tdhB, const float* __restrict__ tdxB,
    const float* __restrict__ wcW, const float* __restrict__ wcB)
{
    __shared__ float dp[4 * Dd * 2], mp[4 * Dd * 2], gxp[4 * Dd * 2];
    const int tid = threadIdx.x;
    const int row0 = blockIdx.x * 8;
    for (int e = tid; e < 8 * Dd; e += 256) {
        int r = e >> 6, k = e & 63;
        dp[(r >> 1) * 128 + k * 2 + (r & 1)] = deltas[(row0 + r) * Dd + k];
        mp[(r >> 1) * 128 + k * 2 + (r & 1)] = masks[(row0 + r) * Dd + k];
    }
    __syncthreads();

    {
        const int c = tid;
        u64 a[4];
        #pragma unroll
        for (int p = 0; p < 4; p++) a[p] = 0ULL;
        #pragma unroll 4
        for (int k = 0; k < Dd; k++) {
            u64 wd = dup2(tdhT_g[k * Hh + c]);
            #pragma unroll
            for (int p = 0; p < 4; p++)
                a[p] = fma2(*(const u64*)(dp + p * 128 + k * 2), wd, a[p]);
        }
        float bb = tdhB[c];
        #pragma unroll
        for (int p = 0; p < 4; p++) {
            float a0, a1; upk2(a[p], a0, a1);
            Gh_g[(row0 + 2 * p)     * Hh + c] = __expf(-fmaxf(a0 + bb, 0.f));
            Gh_g[(row0 + 2 * p + 1) * Hh + c] = __expf(-fmaxf(a1 + bb, 0.f));
        }
    }

    const int j = tid & 63, pg = tid >> 6;
    u64 g = dup2(tdxB[j]);
    #pragma unroll 4
    for (int k = 0; k < Dd; k++)
        g = fma2(*(const u64*)(dp + pg * 128 + k * 2), dup2(tdxT_g[k * Dd + j]), g);
    float g0, g1; upk2(g, g0, g1);
    gxp[pg * 128 + j * 2 + 0] = __expf(-fmaxf(g0, 0.f));
    gxp[pg * 128 + j * 2 + 1] = __expf(-fmaxf(g1, 0.f));
    __syncthreads();
    u64 al = dup2(wcB[j]);
    #pragma unroll 4
    for (int k = 0; k < Dd; k++) {
        al = fma2(*(const u64*)(gxp + pg * 128 + k * 2), dup2(wcW[k * Dd + j]), al);
        al = fma2(*(const u64*)(mp  + pg * 128 + k * 2), dup2(wcW[(Dd + k) * Dd + j]), al);
    }
    float a0, a1; upk2(al, a0, a1);
    alpha_g[(row0 + 2 * pg)     * Dd + j] = a0;
    alpha_g[(row0 + 2 * pg + 1) * Dd + j] = a1;
}

// ============================ main recurrent kernel ============================
// MB=4 rows per CTA, 2 pairs. 256 threads. 2 CTAs/SM.

struct __align__(16) Smem {
    __half histh[Hh * Dd];    // 32 KB  hist_W fp16 [k][j]
    float frT[Dd * Dd];       // 16 KB
    float hp[2 * 2 * Hh];     //  4 KB  h paired [p][c*2+par], p in {0,1}
    float cs[MB * Hh];        //  4 KB
    float zp[2 * 2 * 4 * Hh]; // 16 KB  gate acts [p][col*2+par] (alias: partials)
    float gh[MB * Hh];        //  4 KB  G_h[t+1] staging [r][c]
    float xs[MB * Dd], ms[MB * Dd];
    float mp[2 * 2 * Dd];     // paired m [p][k*2+par]
    float alp[2 * 2 * Dd];
    float xcp[2 * 2 * Dd], xhp[2 * 2 * Dd], ccp[2 * 2 * Dd];
    float hist_b[Dd], fr_b[Dd];
};

// one k-pair (k0, k0+1): wk0/wk1 = uint2 of 4 fp16 cols each; 2 pairs from src
template <int STRIDE>
__device__ __forceinline__ void eblk2(const float* src, int k0,
                                      uint2 wk0, uint2 wk1, u64 (&acc)[4][2]) {
    float2 w0a = __half22float2(*reinterpret_cast<const __half2*>(&wk0.x));
    float2 w0b = __half22float2(*reinterpret_cast<const __half2*>(&wk0.y));
    float2 w1a = __half22float2(*reinterpret_cast<const __half2*>(&wk1.x));
    float2 w1b = __half22float2(*reinterpret_cast<const __half2*>(&wk1.y));
    u64 W0[4] = {dup2(w0a.x), dup2(w0a.y), dup2(w0b.x), dup2(w0b.y)};
    u64 W1[4] = {dup2(w1a.x), dup2(w1a.y), dup2(w1b.x), dup2(w1b.y)};
    #pragma unroll
    for (int p = 0; p < 2; p++) {
        float4 hv = *(const float4*)(src + p * STRIDE + k0 * 2);
        u64 h0 = ((const u64*)&hv)[0];   // k0   (par0, par1)
        u64 h1 = ((const u64*)&hv)[1];   // k0+1
        #pragma unroll
        for (int c = 0; c < 4; c++) {
            acc[c][p] = fma2(h0, W0[c], acc[c][p]);
            acc[c][p] = fma2(h1, W1[c], acc[c][p]);
        }
    }
}

__global__ void __launch_bounds__(NT, 2) rits_kernel(
    const float* __restrict__ values, const float* __restrict__ masks,
    const float* __restrict__ histW, const float* __restrict__ histB,
    const float* __restrict__ frW, const float* __restrict__ frB,
    const float* __restrict__ lstmB,
    const float* __restrict__ outW, const float* __restrict__ outB,
    float* __restrict__ yout, float* __restrict__ impout)
{
    extern __shared__ char smem_raw[];
    Smem& sm = *reinterpret_cast<Smem*>(smem_raw);

    const int t  = threadIdx.x;
    const int b0 = blockIdx.x * MB;

    // ---- stage resident weights & init state ----
    for (int e = t; e < Hh * Dd; e += NT) sm.histh[e] = __float2half(histW[e]);
    for (int e = t; e < Dd * Dd; e += NT) {
        int k = e >> 6, jj = e & 63;
        sm.frT[e] = frW[jj * Dd + k];
    }
    if (t < Dd) { sm.hist_b[t] = histB[t]; sm.fr_b[t] = frB[t]; }
    for (int e = t; e < MB * Hh; e += NT) sm.cs[e] = 0.f;
    for (int e = t; e < 2 * 2 * Hh; e += NT) sm.hp[e] = 0.f;
    {   // step-0 inputs + alpha[0]  (256 threads, one elem each)
        int r = t >> 6, jj = t & 63;
        int off = ((b0 + r) * Tt + 0) * Dd + jj;
        float xv = values[off], mv = masks[off];
        sm.xs[t] = xv; sm.ms[t] = mv;
        sm.mp[(r >> 1) * 128 + jj * 2 + (r & 1)] = mv;
        int j = t & 63, p = (t >> 6) & 1, par = t >> 7;
        sm.alp[p * 128 + j * 2 + par] = alpha_g[((b0 + 2 * p + par) * Tt + 0) * Dd + j];
    }
    // LSTM bias for this thread's 4 output columns (4t..4t+3)
    u64 bq[4];
    #pragma unroll
    for (int c = 0; c < 4; c++) bq[c] = dup2(lstmB[4 * t + c]);
    __syncthreads();

    float pf_x[2], pf_m[2], pf_a[2];   // prefetch regs (threads 128..255)

    for (int step = 0; step < Tt; ++step) {
        // ---- P1 (all 256): x_h partials, k-split 4-way, into zp alias ----
        float2* cpart = (float2*)sm.zp;
        {
            const int j = t & 63, kq = t >> 6;    // kq 0..3
            u64 a[2] = {0ULL, 0ULL};
            const int k0 = kq * 64;
            #pragma unroll 4
            for (int kk = 0; kk < 64; kk++) {
                int k = k0 + kk;
                u64 wd = dup2(__half2float(sm.histh[k * Dd + j]));
                a[0] = fma2(*(const u64*)(sm.hp + 0 * 512 + k * 2), wd, a[0]);
                a[1] = fma2(*(const u64*)(sm.hp + 1 * 512 + k * 2), wd, a[1]);
            }
            #pragma unroll
            for (int p = 0; p < 2; p++) {
                float a0, a1; upk2(a[p], a0, a1);
                cpart[(kq * 2 + p) * 64 + j] = make_float2(a0, a1);
            }
        }
        __syncthreads();

        // ---- P3: threads 0-127 {reduce->x_c; z_h->c_c->impout} | 128-255 {prefetch}
        if (t < 128) {
            const int j = t & 63, p = t >> 6;     // p 0..1
            const float* cp = (const float*)cpart;
            float xh[2];
            #pragma unroll
            for (int par = 0; par < 2; par++) {
                float s = 0.f;
                #pragma unroll
                for (int kq = 0; kq < 4; kq++)
                    s += cp[((kq * 2 + p) * 64 + j) * 2 + par];
                xh[par] = s + sm.hist_b[j];
                int r = 2 * p + par;
                float m = sm.ms[r * Dd + j], x = sm.xs[r * Dd + j];
                float xc = m * x + (1.f - m) * xh[par];
                sm.xcp[p * 128 + j * 2 + par] = xc;
                sm.xhp[p * 128 + j * 2 + par] = xh[par];
            }
            asm volatile("bar.sync 1, 128;" ::: "memory");
            u64 z = dup2(sm.fr_b[j]);
            #pragma unroll 4
            for (int k = 0; k < Dd; k++)
                z = fma2(*(const u64*)(sm.xcp + p * 128 + k * 2),
                         dup2(sm.frT[k * Dd + j]), z);
            float z0, z1; upk2(z, z0, z1);
            float2 al = *(const float2*)(sm.alp + p * 128 + j * 2);
            int r0 = 2 * p, r1 = r0 + 1;
            float m0 = sm.ms[r0 * Dd + j], m1 = sm.ms[r1 * Dd + j];
            float x0 = sm.xs[r0 * Dd + j], x1 = sm.xs[r1 * Dd + j];
            float ch0 = al.x * z0 + (1.f - al.x) * xh[0];
            float ch1 = al.y * z1 + (1.f - al.y) * xh[1];
            float cc0 = m0 * x0 + (1.f - m0) * ch0;
            float cc1 = m1 * x1 + (1.f - m1) * ch1;
            *(float2*)(sm.ccp + p * 128 + j * 2) = make_float2(cc0, cc1);
            impout[(r0 + b0) * Tt * Dd + step * Dd + j] = cc0;
            impout[(r1 + b0) * Tt * Dd + step * Dd + j] = cc1;
        } else if (step + 1 < Tt) {
            const int u = t - 128;
            #pragma unroll
            for (int s = 0; s < 2; s++) {
                int e = u + s * 128;
                int r = e >> 6, jj = e & 63;
                int off = ((b0 + r) * Tt + (step + 1)) * Dd + jj;
                pf_x[s] = values[off]; pf_m[s] = masks[off];
                int p = (e >> 6) & 1, par = e >> 7;
                pf_a[s] = alpha_g[((b0 + 2 * p + par) * Tt + step + 1) * Dd + jj];
            }
            {
                int r = u >> 5, c0 = (u & 31) * 8;
                const float* gsrc = Gh_g + ((b0 + r) * Tt + (step + 1)) * Hh + c0;
                float4 g0 = *(const float4*)gsrc;
                float4 g1 = *(const float4*)(gsrc + 4);
                *(float4*)(sm.gh + r * Hh + c0)     = g0;
                *(float4*)(sm.gh + r * Hh + c0 + 4) = g1;
            }
        }
        __syncthreads();

        // ---- P4 (all 256): z = b + h@Wrk + cc@Wk_cc + m@Wk_m ;
        //      4 cols x 2 pairs per thread; fp16 uint2 weights; dist-8 ----
        {
            u64 acc[4][2];
            #pragma unroll
            for (int c = 0; c < 4; c++) { acc[c][0] = bq[c]; acc[c][1] = bq[c]; }

            // recurrent part, rows 0..255 of WEHrk (uint2 row stride 256)
            const uint2* rk = (const uint2*)WEHrk_g + t;   // this thread's 2 u32
            uint2 a0 = rk[0],        a1 = rk[256];
            uint2 a2 = rk[2 * 256],  a3 = rk[3 * 256];
            uint2 c0 = rk[4 * 256],  c1 = rk[5 * 256];
            uint2 c2 = rk[6 * 256],  c3 = rk[7 * 256];
            #pragma unroll 2
            for (int k = 0; k < Hh; k += 8) {
                int kn = (k + 8) & 255;
                uint2 na0 = rk[kn * 256],       na1 = rk[(kn + 1) * 256];
                uint2 na2 = rk[(kn + 2) * 256], na3 = rk[(kn + 3) * 256];
                eblk2<512>(sm.hp, k,     a0, a1, acc);
                eblk2<512>(sm.hp, k + 2, a2, a3, acc);
                int km = (k + 12) & 255;
                uint2 nc0 = rk[km * 256],       nc1 = rk[(km + 1) * 256];
                uint2 nc2 = rk[(km + 2) * 256], nc3 = rk[(km + 3) * 256];
                eblk2<512>(sm.hp, k + 4, c0, c1, acc);
                eblk2<512>(sm.hp, k + 6, c2, c3, acc);
                a0 = na0; a1 = na1; a2 = na2; a3 = na3;
                c0 = nc0; c1 = nc1; c2 = nc2; c3 = nc3;
            }

            // c_c part, rows 0..63 of WEHk
            const uint2* kk = (const uint2*)WEHk_g + t;
            a0 = kk[0];       a1 = kk[256];
            a2 = kk[2 * 256]; a3 = kk[3 * 256];
            c0 = kk[4 * 256]; c1 = kk[5 * 256];
            c2 = kk[6 * 256]; c3 = kk[7 * 256];
            #pragma unroll 2
            for (int k = 0; k < Dd; k += 8) {
                int kn = (k + 8) & 63;
                uint2 na0 = kk[kn * 256],       na1 = kk[(kn + 1) * 256];
                uint2 na2 = kk[(kn + 2) * 256], na3 = kk[(kn + 3) * 256];
                eblk2<128>(sm.ccp, k,     a0, a1, acc);
                eblk2<128>(sm.ccp, k + 2, a2, a3, acc);
                int km = (k + 12) & 63;
                uint2 nc0 = kk[km * 256],       nc1 = kk[(km + 1) * 256];
                uint2 nc2 = kk[(km + 2) * 256], nc3 = kk[(km + 3) * 256];
                eblk2<128>(sm.ccp, k + 4, c0, c1, acc);
                eblk2<128>(sm.ccp, k + 6, c2, c3, acc);
                a0 = na0; a1 = na1; a2 = na2; a3 = na3;
                c0 = nc0; c1 = nc1; c2 = nc2; c3 = nc3;
            }

            // m part, rows 64..127 of WEHk
            const uint2* km2 = kk + 64 * 256;
            a0 = km2[0];       a1 = km2[256];
            a2 = km2[2 * 256]; a3 = km2[3 * 256];
            c0 = km2[4 * 256]; c1 = km2[5 * 256];
            c2 = km2[6 * 256]; c3 = km2[7 * 256];
            #pragma unroll 2
            for (int k = 0; k < Dd; k += 8) {
                int kn = (k + 8) & 63;
                uint2 na0 = km2[kn * 256],       na1 = km2[(kn + 1) * 256];
                uint2 na2 = km2[(kn + 2) * 256], na3 = km2[(kn + 3) * 256];
                eblk2<128>(sm.mp, k,     a0, a1, acc);
                eblk2<128>(sm.mp, k + 2, a2, a3, acc);
                int km_ = (k + 12) & 63;
                uint2 nc0 = km2[km_ * 256],       nc1 = km2[(km_ + 1) * 256];
                uint2 nc2 = km2[(km_ + 2) * 256], nc3 = km2[(km_ + 3) * 256];
                eblk2<128>(sm.mp, k + 4, c0, c1, acc);
                eblk2<128>(sm.mp, k + 6, c2, c3, acc);
                a0 = na0; a1 = na1; a2 = na2; a3 = na3;
                c0 = nc0; c1 = nc1; c2 = nc2; c3 = nc3;
            }

            // epilogue: activations -> zp  (cols 4t..4t+3, both pairs)
            const int gate = t >> 6;
            #pragma unroll
            for (int p = 0; p < 2; p++) {
                float r8[8];
                #pragma unroll
                for (int c = 0; c < 4; c++) {
                    float v0, v1; upk2(acc[c][p], v0, v1);
                    if (gate == 2) { r8[2 * c] = tanhfast(v0); r8[2 * c + 1] = tanhfast(v1); }
                    else           { r8[2 * c] = sigf(v0);     r8[2 * c + 1] = sigf(v1);     }
                }
                *(float4*)(sm.zp + p * 2048 + 8 * t)     = make_float4(r8[0], r8[1], r8[2], r8[3]);
                *(float4*)(sm.zp + p * 2048 + 8 * t + 4) = make_float4(r8[4], r8[5], r8[6], r8[7]);
            }
        }
        __syncthreads();

        // ---- P5: threads 0-127 {c,h update + fused decay} | 128-255 {commit} --
        if (t < 128) {
            int r = t >> 5;                 // 0..3
            int p = r >> 1, par = r & 1;
            int cb = (t & 31) * 8;
            bool last = (step == Tt - 1);
            float4 gA = *(const float4*)(sm.gh + r * Hh + cb);
            float4 gB = *(const float4*)(sm.gh + r * Hh + cb + 4);
            float gv8[8] = {gA.x, gA.y, gA.z, gA.w, gB.x, gB.y, gB.z, gB.w};
            #pragma unroll
            for (int cc = 0; cc < 8; cc++) {
                int c = cb + cc;
                float iv = sm.zp[p * 2048 + (0 * Hh + c) * 2 + par];
                float fv = sm.zp[p * 2048 + (1 * Hh + c) * 2 + par];
                float gg = sm.zp[p * 2048 + (2 * Hh + c) * 2 + par];
                float ov = sm.zp[p * 2048 + (3 * Hh + c) * 2 + par];
                float cold = sm.cs[r * Hh + c];
                float cnew = fv * cold + iv * gg;
                sm.cs[r * Hh + c] = cnew;
                float hh = ov * tanhfast(cnew);
                if (!last) hh *= gv8[cc];
                sm.hp[p * 512 + c * 2 + par] = hh;
            }
        } else if (step + 1 < Tt) {
            const int u = t - 128;
            #pragma unroll
            for (int s = 0; s < 2; s++) {
                int e = u + s * 128;
                int r = e >> 6, jj = e & 63;
                sm.xs[e] = pf_x[s]; sm.ms[e] = pf_m[s];
                sm.mp[(r >> 1) * 128 + jj * 2 + (r & 1)] = pf_m[s];
                int p = (e >> 6) & 1, par = e >> 7;
                sm.alp[p * 128 + jj * 2 + par] = pf_a[s];
            }
        }
        __syncthreads();
    }

    // ---- final: y = h @ out_W + out_b ----
    {
        int w = t >> 5, lane = t & 31;
        if (w < MB) {
            float s = 0.f;
            for (int k = lane; k < Hh; k += 32)
                s += sm.hp[(w >> 1) * 512 + k * 2 + (w & 1)] * outW[k];
            #pragma unroll
            for (int o = 16; o > 0; o >>= 1)
                s += __shfl_down_sync(0xffffffffu, s, o);
            if (lane == 0) yout[b0 + w] = s + outB[0];
        }
    }
}

// ================================ launcher ================================

extern "C" void kernel_launch(void* const* d_in, const int* in_sizes, int n_in,
                              void* d_out, int out_size) {
    const float* values = (const float*)d_in[0];
    const float* masks  = (const float*)d_in[1];
    const float* deltas = (const float*)d_in[2];
    const float* tdhW   = (const float*)d_in[3];
    const float* tdhB   = (const float*)d_in[4];
    const float* tdxW   = (const float*)d_in[5];
    const float* tdxB   = (const float*)d_in[6];
    const float* histW  = (const float*)d_in[7];
    const float* histB  = (const float*)d_in[8];
    const float* frW    = (const float*)d_in[9];
    const float* frB    = (const float*)d_in[10];
    const float* wcW    = (const float*)d_in[11];
    const float* wcB    = (const float*)d_in[12];
    const float* lstmK  = (const float*)d_in[13];
    const float* lstmRK = (const float*)d_in[14];
    const float* lstmB  = (const float*)d_in[15];
    const float* outW   = (const float*)d_in[16];
    const float* outB   = (const float*)d_in[17];

    float* yout   = (float*)d_out;       // y_h [B,1] first
    float* impout = yout + Bsz;          // imputations [B,T,D]

    transpose_kernel<<<(Hh * Dd + Dd * Dd + 255) / 256, 256>>>(tdhW, tdxW);
    pack_h_kernel<<<(384 * 1024 + 255) / 256, 256>>>(lstmRK, lstmK);
    pre_ga_kernel<<<Bsz * Tt / 8, 256>>>(deltas, masks, tdhB, tdxB, wcW, wcB);

    cudaFuncSetAttribute(rits_kernel, cudaFuncAttributeMaxDynamicSharedMemorySize,
                         (int)sizeof(Smem));
    rits_kernel<<<GRID, NT, sizeof(Smem)>>>(
        values, masks, histW, histB, frW, frB,
        lstmB, outW, outB, yout, impout);
}

// round 15
// speedup vs baseline: 2.2750x; 2.2750x over previous
#include <cuda_runtime.h>
#include <cuda_fp16.h>
#include <cstdint>

#define Bsz 1024
#define Tt  128
#define Dd  64
#define Hh  256
#define MB  8
#define NT  512
#define GRID 128
#define BSTR 392   // Bsm row stride in halfs (4*98 -> conflict-free fragment loads)

typedef unsigned long long u64;

// ------------------- device scratch -------------------
__device__ float tdhT_g[Dd * Hh];        // td_h_W^T  [k][c]
__device__ float tdxT_g[Dd * Dd];        // td_x_W^T  [k][j]
__device__ float Gh_g[Bsz * Tt * Hh];    // gamma_h
__device__ float alpha_g[Bsz * Tt * Dd]; // alpha
// A = W^T fp16 packed in m16n8k16 A-fragment order:
// u32 index = (((w*24 + ks)*4 + mt)*32 + lane)*4 + reg
__device__ uint32_t WA_g[16 * 24 * 4 * 32 * 4];

__device__ __forceinline__ u64 dup2(float w) {
    u64 r; asm("mov.b64 %0, {%1,%1};" : "=l"(r) : "f"(w)); return r;
}
__device__ __forceinline__ void upk2(u64 v, float& lo, float& hi) {
    asm("mov.b64 {%0,%1}, %2;" : "=f"(lo), "=f"(hi) : "l"(v));
}
__device__ __forceinline__ u64 fma2(u64 a, u64 b, u64 c) {
    u64 d; asm("fma.rn.f32x2 %0, %1, %2, %3;" : "=l"(d) : "l"(a), "l"(b), "l"(c)); return d;
}
__device__ __forceinline__ float sigf(float x) {
    return __fdividef(1.f, 1.f + __expf(-x));
}
__device__ __forceinline__ float tanhfast(float x) {
    return __fdividef(2.f, 1.f + __expf(-2.f * x)) - 1.f;
}

#define HMMA(c, a, b0_, b1_) \
    asm volatile("mma.sync.aligned.m16n8k16.row.col.f32.f16.f16.f32 " \
        "{%0,%1,%2,%3}, {%4,%5,%6,%7}, {%8,%9}, {%0,%1,%2,%3};" \
        : "+f"((c)[0]), "+f"((c)[1]), "+f"((c)[2]), "+f"((c)[3]) \
        : "r"((a).x), "r"((a).y), "r"((a).z), "r"((a).w), "r"(b0_), "r"(b1_))

// ============================ precompute kernels ============================

__global__ void transpose_kernel(const float* __restrict__ tdhW,
                                 const float* __restrict__ tdxW) {
    int idx = blockIdx.x * 256 + threadIdx.x;
    if (idx < Hh * Dd) {
        int c = idx >> 6, k = idx & 63;
        tdhT_g[k * Hh + c] = tdhW[idx];
    } else if (idx < Hh * Dd + Dd * Dd) {
        int e = idx - Hh * Dd;
        int j = e >> 6, k = e & 63;
        tdxT_g[k * Dd + j] = tdxW[e];
    }
}

// Pack W^T into A-fragment order. k-axis: [cc(0..63) | mask(64..127) | h(128..383)]
// W^T[m][k]: k<128 -> lstmK[k][m]; else lstmRK[k-128][m].
__global__ void pack_wt_kernel(const float* __restrict__ lstmK,
                               const float* __restrict__ lstmRK) {
    int idx = blockIdx.x * 256 + threadIdx.x;     // 196608 u32 total
    if (idx >= 16 * 24 * 4 * 32 * 4) return;
    int u = idx;
    int reg  = u & 3;  u >>= 2;
    int lane = u & 31; u >>= 5;
    int mt   = u & 3;  u >>= 2;
    int ks   = u % 24;
    int w    = u / 24;
    int g = lane >> 2, tig = lane & 3;
    int m = w * 64 + mt * 16 + g + ((reg & 1) ? 8 : 0);
    int k = ks * 16 + tig * 2 + ((reg & 2) ? 8 : 0);
    float v0 = (k     < 128) ? lstmK[k * 1024 + m]       : lstmRK[(k - 128) * 1024 + m];
    float v1 = (k + 1 < 128) ? lstmK[(k + 1) * 1024 + m] : lstmRK[(k + 1 - 128) * 1024 + m];
    __half2 h2 = __floats2half2_rn(v0, v1);
    WA_g[idx] = *reinterpret_cast<uint32_t*>(&h2);
}

__global__ void __launch_bounds__(256) pre_ga_kernel(
    const float* __restrict__ deltas, const float* __restrict__ masks,
    const float* __restrict__ tdhB, const float* __restrict__ tdxB,
    const float* __restrict__ wcW, const float* __restrict__ wcB)
{
    __shared__ float dp[4 * Dd * 2], mp[4 * Dd * 2], gxp[4 * Dd * 2];
    const int tid = threadIdx.x;
    const int row0 = blockIdx.x * 8;
    for (int e = tid; e < 8 * Dd; e += 256) {
        int r = e >> 6, k = e & 63;
        dp[(r >> 1) * 128 + k * 2 + (r & 1)] = deltas[(row0 + r) * Dd + k];
        mp[(r >> 1) * 128 + k * 2 + (r & 1)] = masks[(row0 + r) * Dd + k];
    }
    __syncthreads();
    {
        const int c = tid;
        u64 a[4];
        #pragma unroll
        for (int p = 0; p < 4; p++) a[p] = 0ULL;
        #pragma unroll 4
        for (int k = 0; k < Dd; k++) {
            u64 wd = dup2(tdhT_g[k * Hh + c]);
            #pragma unroll
            for (int p = 0; p < 4; p++)
                a[p] = fma2(*(const u64*)(dp + p * 128 + k * 2), wd, a[p]);
        }
        float bb = tdhB[c];
        #pragma unroll
        for (int p = 0; p < 4; p++) {
            float a0, a1; upk2(a[p], a0, a1);
            Gh_g[(row0 + 2 * p)     * Hh + c] = __expf(-fmaxf(a0 + bb, 0.f));
            Gh_g[(row0 + 2 * p + 1) * Hh + c] = __expf(-fmaxf(a1 + bb, 0.f));
        }
    }
    const int j = tid & 63, pg = tid >> 6;
    u64 g = dup2(tdxB[j]);
    #pragma unroll 4
    for (int k = 0; k < Dd; k++)
        g = fma2(*(const u64*)(dp + pg * 128 + k * 2), dup2(tdxT_g[k * Dd + j]), g);
    float g0, g1; upk2(g, g0, g1);
    gxp[pg * 128 + j * 2 + 0] = __expf(-fmaxf(g0, 0.f));
    gxp[pg * 128 + j * 2 + 1] = __expf(-fmaxf(g1, 0.f));
    __syncthreads();
    u64 al = dup2(wcB[j]);
    #pragma unroll 4
    for (int k = 0; k < Dd; k++) {
        al = fma2(*(const u64*)(gxp + pg * 128 + k * 2), dup2(wcW[k * Dd + j]), al);
        al = fma2(*(const u64*)(mp  + pg * 128 + k * 2), dup2(wcW[(Dd + k) * Dd + j]), al);
    }
    float a0, a1; upk2(al, a0, a1);
    alpha_g[(row0 + 2 * pg)     * Dd + j] = a0;
    alpha_g[(row0 + 2 * pg + 1) * Dd + j] = a1;
}

// ============================ main recurrent kernel ============================

struct __align__(16) Smem {
    __half Bsm[8 * BSTR];     // 6.3 KB  B: [n(batch row 0..7)][k 0..383], stride 392
    float hist[Hh * Dd];      // 64 KB
    float frT[Dd * Dd];       // 16 KB
    float hp[4 * 2 * Hh];     //  8 KB  h fp32 paired [p][c*2+par]
    float cs[MB * Hh];        //  8 KB
    float zp[4 * 2 * 4 * Hh]; // 32 KB  gate acts (alias: x_h partials)
    float gh[MB * Hh];        //  8 KB
    float lb[1024];           //  4 KB
    float xs[MB * Dd], ms[MB * Dd];
    float alp[4 * 2 * Dd], xcp[4 * 2 * Dd], xhp[4 * 2 * Dd];
    float hist_b[Dd], fr_b[Dd];
};

__device__ __forceinline__ void bsm_put(Smem& sm, int r, int k, float v) {
    sm.Bsm[r * BSTR + k] = __float2half(v);
}

__global__ void __launch_bounds__(NT, 1) rits_kernel(
    const float* __restrict__ values, const float* __restrict__ masks,
    const float* __restrict__ histW, const float* __restrict__ histB,
    const float* __restrict__ frW, const float* __restrict__ frB,
    const float* __restrict__ lstmB,
    const float* __restrict__ outW, const float* __restrict__ outB,
    float* __restrict__ yout, float* __restrict__ impout)
{
    extern __shared__ char smem_raw[];
    Smem& sm = *reinterpret_cast<Smem*>(smem_raw);

    const int t  = threadIdx.x;
    const int b0 = blockIdx.x * MB;

    // ---- stage resident weights & init state ----
    for (int e = t; e < Hh * Dd; e += NT) sm.hist[e] = histW[e];
    for (int e = t; e < Dd * Dd; e += NT) {
        int k = e >> 6, jj = e & 63;
        sm.frT[e] = frW[jj * Dd + k];
    }
    for (int e = t; e < 1024; e += NT) sm.lb[e] = lstmB[e];
    if (t < Dd) { sm.hist_b[t] = histB[t]; sm.fr_b[t] = frB[t]; }
    for (int e = t; e < MB * Hh; e += NT) sm.cs[e] = 0.f;
    for (int e = t; e < 4 * 2 * Hh; e += NT) sm.hp[e] = 0.f;
    for (int e = t; e < 8 * BSTR; e += NT) sm.Bsm[e] = __float2half(0.f);
    {   // step-0 inputs + alpha[0]
        int r = t >> 6, jj = t & 63;
        int off = ((b0 + r) * Tt + 0) * Dd + jj;
        sm.xs[t] = values[off]; sm.ms[t] = masks[off];
        int j = t & 63, p = (t >> 6) & 3, par = t >> 8;
        sm.alp[p * 128 + j * 2 + par] = alpha_g[((b0 + 2 * p + par) * Tt + 0) * Dd + j];
    }
    __syncthreads();
    {   // mask into B (k 64..127) after zero-fill
        int r = t >> 6, jj = t & 63;
        bsm_put(sm, r, 64 + jj, sm.ms[t]);
    }
    __syncthreads();

    float pf_x[2], pf_m[2], pf_a0, pf_a1;

    const int w = t >> 5, lane = t & 31;
    const int g = lane >> 2, tig = lane & 3;
    const uint4* Aw = reinterpret_cast<const uint4*>(WA_g) + (size_t)w * 24 * 4 * 32 + lane;

    for (int step = 0; step < Tt; ++step) {
        // ---- P1: x_h partials, k-split 8-way, into zp alias ----
        float2* cpart = (float2*)sm.zp;
        {
            const int j = t & 63, kq = t >> 6;
            u64 a[4];
            #pragma unroll
            for (int p = 0; p < 4; p++) a[p] = 0ULL;
            const int k0 = kq * 32;
            #pragma unroll 4
            for (int kk = 0; kk < 32; kk++) {
                int k = k0 + kk;
                u64 wd = dup2(sm.hist[k * Dd + j]);
                #pragma unroll
                for (int p = 0; p < 4; p++)
                    a[p] = fma2(*(const u64*)(sm.hp + p * 512 + k * 2), wd, a[p]);
            }
            #pragma unroll
            for (int p = 0; p < 4; p++) {
                float a0, a1; upk2(a[p], a0, a1);
                cpart[(kq * 4 + p) * 64 + j] = make_float2(a0, a1);
            }
        }
        __syncthreads();

        // ---- P3: wg0 {x_c; z_h -> c_c -> B + impout} | wg1 {prefetch} ----
        if (t < 256) {
            const int j = t & 63, p = t >> 6;
            const float* cp = (const float*)cpart;
            float xh[2];
            #pragma unroll
            for (int par = 0; par < 2; par++) {
                float s = 0.f;
                #pragma unroll
                for (int kq = 0; kq < 8; kq++)
                    s += cp[((kq * 4 + p) * 64 + j) * 2 + par];
                xh[par] = s + sm.hist_b[j];
                int r = 2 * p + par;
                float m = sm.ms[r * Dd + j], x = sm.xs[r * Dd + j];
                float xc = m * x + (1.f - m) * xh[par];
                sm.xcp[p * 128 + j * 2 + par] = xc;
                sm.xhp[p * 128 + j * 2 + par] = xh[par];
            }
            asm volatile("bar.sync 1, 256;" ::: "memory");
            u64 z = dup2(sm.fr_b[j]);
            #pragma unroll 4
            for (int k = 0; k < Dd; k++)
                z = fma2(*(const u64*)(sm.xcp + p * 128 + k * 2),
                         dup2(sm.frT[k * Dd + j]), z);
            float z0, z1; upk2(z, z0, z1);
            float2 al = *(const float2*)(sm.alp + p * 128 + j * 2);
            int r0 = 2 * p, r1 = r0 + 1;
            float m0 = sm.ms[r0 * Dd + j], m1 = sm.ms[r1 * Dd + j];
            float x0 = sm.xs[r0 * Dd + j], x1 = sm.xs[r1 * Dd + j];
            float ch0 = al.x * z0 + (1.f - al.x) * xh[0];
            float ch1 = al.y * z1 + (1.f - al.y) * xh[1];
            float cc0 = m0 * x0 + (1.f - m0) * ch0;
            float cc1 = m1 * x1 + (1.f - m1) * ch1;
            bsm_put(sm, r0, j, cc0);
            bsm_put(sm, r1, j, cc1);
            impout[(r0 + b0) * Tt * Dd + step * Dd + j] = cc0;
            impout[(r1 + b0) * Tt * Dd + step * Dd + j] = cc1;
        } else if (step + 1 < Tt) {
            const int u = t - 256;
            #pragma unroll
            for (int s = 0; s < 2; s++) {
                int e = u + s * 256;
                int r = e >> 6, jj = e & 63;
                int off = ((b0 + r) * Tt + (step + 1)) * Dd + jj;
                pf_x[s] = values[off]; pf_m[s] = masks[off];
            }
            {
                int j = u & 63, rp = u >> 6;
                pf_a0 = alpha_g[((b0 + 2 * rp)     * Tt + step + 1) * Dd + j];
                pf_a1 = alpha_g[((b0 + 2 * rp + 1) * Tt + step + 1) * Dd + j];
            }
            {
                int r = u >> 5, c0 = (u & 31) * 8;
                const float* gsrc = Gh_g + ((b0 + r) * Tt + (step + 1)) * Hh + c0;
                float4 g0 = *(const float4*)gsrc;
                float4 g1 = *(const float4*)(gsrc + 4);
                *(float4*)(sm.gh + r * Hh + c0)     = g0;
                *(float4*)(sm.gh + r * Hh + c0 + 4) = g1;
            }
        }
        __syncthreads();

        // ---- P4: HMMA GEMM z^T[1024x8] = W^T @ [cc|m|h]^T; warp = 64 M-rows ----
        {
            float acc[4][4];
            #pragma unroll
            for (int mt = 0; mt < 4; mt++)
                #pragma unroll
                for (int q = 0; q < 4; q++) acc[mt][q] = 0.f;

            const __half* Brow = sm.Bsm + g * BSTR;
            uint4 Ab0 = Aw[0], Ab1 = Aw[32], Ab2 = Aw[64], Ab3 = Aw[96];
            #pragma unroll 2
            for (int ks = 0; ks < 24; ks++) {
                int kn = (ks + 1 < 24) ? (ks + 1) : 0;
                const uint4* Ap = Aw + kn * 128;
                uint4 An0 = Ap[0], An1 = Ap[32], An2 = Ap[64], An3 = Ap[96];
                uint32_t b0 = *(const uint32_t*)(Brow + ks * 16 + tig * 2);
                uint32_t b1 = *(const uint32_t*)(Brow + ks * 16 + tig * 2 + 8);
                HMMA(acc[0], Ab0, b0, b1);
                HMMA(acc[1], Ab1, b0, b1);
                HMMA(acc[2], Ab2, b0, b1);
                HMMA(acc[3], Ab3, b0, b1);
                Ab0 = An0; Ab1 = An1; Ab2 = An2; Ab3 = An3;
            }
            // epilogue: bias + activation -> zp[pair=tig][col=m, par=n&1]
            #pragma unroll
            for (int mt = 0; mt < 4; mt++) {
                int mbase = w * 64 + mt * 16 + g;
                #pragma unroll
                for (int hf = 0; hf < 2; hf++) {
                    int m = mbase + hf * 8;
                    float bias = sm.lb[m];
                    float v0 = acc[mt][hf * 2 + 0] + bias;
                    float v1 = acc[mt][hf * 2 + 1] + bias;
                    int gate = m >> 8;
                    float a0, a1;
                    if (gate == 2) { a0 = tanhfast(v0); a1 = tanhfast(v1); }
                    else           { a0 = sigf(v0);     a1 = sigf(v1);     }
                    *(float2*)(sm.zp + tig * 2048 + m * 2) = make_float2(a0, a1);
                }
            }
        }
        __syncthreads();

        // ---- P5: wg0 {c,h update + fused decay -> hp fp32 + B fp16} | wg1 {commit}
        if (t < 256) {
            int r = t >> 5;
            int p = r >> 1, par = r & 1;
            int cb = (t & 31) * 8;
            bool last = (step == Tt - 1);
            float4 gA = *(const float4*)(sm.gh + r * Hh + cb);
            float4 gB = *(const float4*)(sm.gh + r * Hh + cb + 4);
            float gv8[8] = {gA.x, gA.y, gA.z, gA.w, gB.x, gB.y, gB.z, gB.w};
            #pragma unroll
            for (int cc = 0; cc < 8; cc++) {
                int c = cb + cc;
                float iv = sm.zp[p * 2048 + (0 * Hh + c) * 2 + par];
                float fv = sm.zp[p * 2048 + (1 * Hh + c) * 2 + par];
                float gg = sm.zp[p * 2048 + (2 * Hh + c) * 2 + par];
                float ov = sm.zp[p * 2048 + (3 * Hh + c) * 2 + par];
                float cold = sm.cs[r * Hh + c];
                float cnew = fv * cold + iv * gg;
                sm.cs[r * Hh + c] = cnew;
                float hh = ov * tanhfast(cnew);
                if (!last) hh *= gv8[cc];
                sm.hp[p * 512 + c * 2 + par] = hh;
                bsm_put(sm, r, 128 + c, hh);
            }
        } else if (step + 1 < Tt) {
            const int u = t - 256;
            #pragma unroll
            for (int s = 0; s < 2; s++) {
                int e = u + s * 256;
                int r = e >> 6, jj = e & 63;
                sm.xs[e] = pf_x[s]; sm.ms[e] = pf_m[s];
                bsm_put(sm, r, 64 + jj, pf_m[s]);
            }
            int j = u & 63, rp = u >> 6;
            *(float2*)(sm.alp + rp * 128 + j * 2) = make_float2(pf_a0, pf_a1);
        }
        __syncthreads();
    }

    // ---- final: y = h @ out_W + out_b ----
    {
        int ww = t >> 5, ll = t & 31;
        if (ww < MB) {
            float s = 0.f;
            for (int k = ll; k < Hh; k += 32)
                s += sm.hp[(ww >> 1) * 512 + k * 2 + (ww & 1)] * outW[k];
            #pragma unroll
            for (int o = 16; o > 0; o >>= 1)
                s += __shfl_down_sync(0xffffffffu, s, o);
            if (ll == 0) yout[b0 + ww] = s + outB[0];
        }
    }
}

// ================================ launcher ================================

extern "C" void kernel_launch(void* const* d_in, const int* in_sizes, int n_in,
                              void* d_out, int out_size) {
    const float* values = (const float*)d_in[0];
    const float* masks  = (const float*)d_in[1];
    const float* deltas = (const float*)d_in[2];
    const float* tdhW   = (const float*)d_in[3];
    const float* tdhB   = (const float*)d_in[4];
    const float* tdxW   = (const float*)d_in[5];
    const float* tdxB   = (const float*)d_in[6];
    const float* histW  = (const float*)d_in[7];
    const float* histB  = (const float*)d_in[8];
    const float* frW    = (const float*)d_in[9];
    const float* frB    = (const float*)d_in[10];
    const float* wcW    = (const float*)d_in[11];
    const float* wcB    = (const float*)d_in[12];
    const float* lstmK  = (const float*)d_in[13];
    const float* lstmRK = (const float*)d_in[14];
    const float* lstmB  = (const float*)d_in[15];
    const float* outW   = (const float*)d_in[16];
    const float* outB   = (const float*)d_in[17];

    float* yout   = (float*)d_out;       // y_h [B,1]
    float* impout = yout + Bsz;          // imputations [B,T,D]

    transpose_kernel<<<(Hh * Dd + Dd * Dd + 255) / 256, 256>>>(tdhW, tdxW);
    pack_wt_kernel<<<(16 * 24 * 4 * 32 * 4 + 255) / 256, 256>>>(lstmK, lstmRK);
    pre_ga_kernel<<<Bsz * Tt / 8, 256>>>(deltas, masks, tdhB, tdxB, wcW, wcB);

    cudaFuncSetAttribute(rits_kernel, cudaFuncAttributeMaxDynamicSharedMemorySize,
                         (int)sizeof(Smem));
    rits_kernel<<<GRID, NT, sizeof(Smem)>>>(
        values, masks, histW, histB, frW, frB,
        lstmB, outW, outB, yout, impout);
}

// round 16
// speedup vs baseline: 2.5356x; 1.1145x over previous
#include <cuda_runtime.h>
#include <cuda_fp16.h>
#include <cstdint>

#define Bsz 1024
#define Tt  128
#define Dd  64
#define Hh  256
#define MB  8
#define NT  512
#define GRID 128
#define BSTR 392   // Bsm row stride in halfs (conflict-free fragment loads)

typedef unsigned long long u64;

// ------------------- device scratch -------------------
__device__ float tdhT_g[Dd * Hh];        // td_h_W^T  [k][c]
__device__ float tdxT_g[Dd * Dd];        // td_x_W^T  [k][j]
__device__ float Gh_g[Bsz * Tt * Hh];    // gamma_h
__device__ float alpha_g[Bsz * Tt * Dd]; // alpha
// A = W^T fp16 in m16n8k16 A-fragment order: (((w*24+ks)*4+mt)*32+lane)*4+reg
__device__ uint32_t WA_g[16 * 24 * 4 * 32 * 4];
// hist^T fp16 fragments: ((mt*16+ksg)*32+lane)*4+reg   (mt 0..3, ksg 0..15)
__device__ uint32_t HA_g[4 * 16 * 32 * 4];

__device__ __forceinline__ u64 dup2(float w) {
    u64 r; asm("mov.b64 %0, {%1,%1};" : "=l"(r) : "f"(w)); return r;
}
__device__ __forceinline__ void upk2(u64 v, float& lo, float& hi) {
    asm("mov.b64 {%0,%1}, %2;" : "=f"(lo), "=f"(hi) : "l"(v));
}
__device__ __forceinline__ u64 fma2(u64 a, u64 b, u64 c) {
    u64 d; asm("fma.rn.f32x2 %0, %1, %2, %3;" : "=l"(d) : "l"(a), "l"(b), "l"(c)); return d;
}
__device__ __forceinline__ float sigf(float x) {
    return __fdividef(1.f, 1.f + __expf(-x));
}
__device__ __forceinline__ float tanhfast(float x) {
    return __fdividef(2.f, 1.f + __expf(-2.f * x)) - 1.f;
}

#define HMMA(c, a, b0_, b1_) \
    asm volatile("mma.sync.aligned.m16n8k16.row.col.f32.f16.f16.f32 " \
        "{%0,%1,%2,%3}, {%4,%5,%6,%7}, {%8,%9}, {%0,%1,%2,%3};" \
        : "+f"((c)[0]), "+f"((c)[1]), "+f"((c)[2]), "+f"((c)[3]) \
        : "r"((a).x), "r"((a).y), "r"((a).z), "r"((a).w), "r"(b0_), "r"(b1_))

// ============================ precompute kernels ============================

__global__ void transpose_kernel(const float* __restrict__ tdhW,
                                 const float* __restrict__ tdxW) {
    int idx = blockIdx.x * 256 + threadIdx.x;
    if (idx < Hh * Dd) {
        int c = idx >> 6, k = idx & 63;
        tdhT_g[k * Hh + c] = tdhW[idx];
    } else if (idx < Hh * Dd + Dd * Dd) {
        int e = idx - Hh * Dd;
        int j = e >> 6, k = e & 63;
        tdxT_g[k * Dd + j] = tdxW[e];
    }
}

// Pack W^T (LSTM) and hist^T into A-fragment order.
// k-axis of W^T: [cc(0..63) | mask(64..127) | h(128..383)]
__global__ void pack_wt_kernel(const float* __restrict__ lstmK,
                               const float* __restrict__ lstmRK,
                               const float* __restrict__ histW) {
    const int NWA = 16 * 24 * 4 * 32 * 4;
    int idx = blockIdx.x * 256 + threadIdx.x;
    if (idx < NWA) {
        int u = idx;
        int reg  = u & 3;  u >>= 2;
        int lane = u & 31; u >>= 5;
        int mt   = u & 3;  u >>= 2;
        int ks   = u % 24;
        int w    = u / 24;
        int g = lane >> 2, tig = lane & 3;
        int m = w * 64 + mt * 16 + g + ((reg & 1) ? 8 : 0);
        int k = ks * 16 + tig * 2 + ((reg & 2) ? 8 : 0);
        float v0 = (k     < 128) ? lstmK[k * 1024 + m]       : lstmRK[(k - 128) * 1024 + m];
        float v1 = (k + 1 < 128) ? lstmK[(k + 1) * 1024 + m] : lstmRK[(k + 1 - 128) * 1024 + m];
        __half2 h2 = __floats2half2_rn(v0, v1);
        WA_g[idx] = *reinterpret_cast<uint32_t*>(&h2);
    } else if (idx < NWA + 4 * 16 * 32 * 4) {
        int u = idx - NWA;
        int reg  = u & 3;  u >>= 2;
        int lane = u & 31; u >>= 5;
        int ksg  = u & 15; u >>= 4;
        int mt   = u;
        int g = lane >> 2, tig = lane & 3;
        int m = mt * 16 + g + ((reg & 1) ? 8 : 0);        // feature j 0..63
        int k = ksg * 16 + tig * 2 + ((reg & 2) ? 8 : 0); // h index 0..255
        float v0 = histW[k * Dd + m];
        float v1 = histW[(k + 1) * Dd + m];
        __half2 h2 = __floats2half2_rn(v0, v1);
        HA_g[idx - NWA] = *reinterpret_cast<uint32_t*>(&h2);
    }
}

__global__ void __launch_bounds__(256) pre_ga_kernel(
    const float* __restrict__ deltas, const float* __restrict__ masks,
    const float* __restrict__ tdhB, const float* __restrict__ tdxB,
    const float* __restrict__ wcW, const float* __restrict__ wcB)
{
    __shared__ float dp[4 * Dd * 2], mp[4 * Dd * 2], gxp[4 * Dd * 2];
    const int tid = threadIdx.x;
    const int row0 = blockIdx.x * 8;
    for (int e = tid; e < 8 * Dd; e += 256) {
        int r = e >> 6, k = e & 63;
        dp[(r >> 1) * 128 + k * 2 + (r & 1)] = deltas[(row0 + r) * Dd + k];
        mp[(r >> 1) * 128 + k * 2 + (r & 1)] = masks[(row0 + r) * Dd + k];
    }
    __syncthreads();
    {
        const int c = tid;
        u64 a[4];
        #pragma unroll
        for (int p = 0; p < 4; p++) a[p] = 0ULL;
        #pragma unroll 4
        for (int k = 0; k < Dd; k++) {
            u64 wd = dup2(tdhT_g[k * Hh + c]);
            #pragma unroll
            for (int p = 0; p < 4; p++)
                a[p] = fma2(*(const u64*)(dp + p * 128 + k * 2), wd, a[p]);
        }
        float bb = tdhB[c];
        #pragma unroll
        for (int p = 0; p < 4; p++) {
            float a0, a1; upk2(a[p], a0, a1);
            Gh_g[(row0 + 2 * p)     * Hh + c] = __expf(-fmaxf(a0 + bb, 0.f));
            Gh_g[(row0 + 2 * p + 1) * Hh + c] = __expf(-fmaxf(a1 + bb, 0.f));
        }
    }
    const int j = tid & 63, pg = tid >> 6;
    u64 g = dup2(tdxB[j]);
    #pragma unroll 4
    for (int k = 0; k < Dd; k++)
        g = fma2(*(const u64*)(dp + pg * 128 + k * 2), dup2(tdxT_g[k * Dd + j]), g);
    float g0, g1; upk2(g, g0, g1);
    gxp[pg * 128 + j * 2 + 0] = __expf(-fmaxf(g0, 0.f));
    gxp[pg * 128 + j * 2 + 1] = __expf(-fmaxf(g1, 0.f));
    __syncthreads();
    u64 al = dup2(wcB[j]);
    #pragma unroll 4
    for (int k = 0; k < Dd; k++) {
        al = fma2(*(const u64*)(gxp + pg * 128 + k * 2), dup2(wcW[k * Dd + j]), al);
        al = fma2(*(const u64*)(mp  + pg * 128 + k * 2), dup2(wcW[(Dd + k) * Dd + j]), al);
    }
    float a0, a1; upk2(al, a0, a1);
    alpha_g[(row0 + 2 * pg)     * Dd + j] = a0;
    alpha_g[(row0 + 2 * pg + 1) * Dd + j] = a1;
}

// ============================ main recurrent kernel ============================

struct __align__(16) Smem {
    __half Bsm[8 * BSTR];     // 6.3 KB  B: [n(row 0..7)][k 0..383 = cc|m|h]
    float frT[Dd * Dd];       // 16 KB
    float hp[4 * 2 * Hh];     //  8 KB  final-step h (for y)
    float cs[MB * Hh];        //  8 KB
    float zp[4 * 2 * 4 * Hh]; // 32 KB  gate acts (alias: x_h partials)
    float gh[MB * Hh];        //  8 KB
    float lb[1024];           //  4 KB
    float xs[MB * Dd], ms[MB * Dd];
    float alp[4 * 2 * Dd], xcp[4 * 2 * Dd], xhp[4 * 2 * Dd];
    float hist_b[Dd], fr_b[Dd];
};

__device__ __forceinline__ void bsm_put(Smem& sm, int r, int k, float v) {
    sm.Bsm[r * BSTR + k] = __float2half(v);
}

__global__ void __launch_bounds__(NT, 1) rits_kernel(
    const float* __restrict__ values, const float* __restrict__ masks,
    const float* __restrict__ histB,
    const float* __restrict__ frW, const float* __restrict__ frB,
    const float* __restrict__ lstmB,
    const float* __restrict__ outW, const float* __restrict__ outB,
    float* __restrict__ yout, float* __restrict__ impout)
{
    extern __shared__ char smem_raw[];
    Smem& sm = *reinterpret_cast<Smem*>(smem_raw);

    const int t  = threadIdx.x;
    const int b0 = blockIdx.x * MB;

    // ---- stage resident weights & init state ----
    for (int e = t; e < Dd * Dd; e += NT) {
        int k = e >> 6, jj = e & 63;
        sm.frT[e] = frW[jj * Dd + k];
    }
    for (int e = t; e < 1024; e += NT) sm.lb[e] = lstmB[e];
    if (t < Dd) { sm.hist_b[t] = histB[t]; sm.fr_b[t] = frB[t]; }
    for (int e = t; e < MB * Hh; e += NT) sm.cs[e] = 0.f;
    for (int e = t; e < 4 * 2 * Hh; e += NT) sm.hp[e] = 0.f;
    for (int e = t; e < 8 * BSTR; e += NT) sm.Bsm[e] = __float2half(0.f);
    {   // step-0 inputs + alpha[0]
        int r = t >> 6, jj = t & 63;
        int off = ((b0 + r) * Tt + 0) * Dd + jj;
        sm.xs[t] = values[off]; sm.ms[t] = masks[off];
        int j = t & 63, p = (t >> 6) & 3, par = t >> 8;
        sm.alp[p * 128 + j * 2 + par] = alpha_g[((b0 + 2 * p + par) * Tt + 0) * Dd + j];
    }
    __syncthreads();
    {   // mask into B (k 64..127) after zero-fill
        int r = t >> 6, jj = t & 63;
        bsm_put(sm, r, 64 + jj, sm.ms[t]);
    }
    __syncthreads();

    float pf_x[2], pf_m[2], pf_a0, pf_a1;

    const int w = t >> 5, lane = t & 31;
    const int g = lane >> 2, tig = lane & 3;
    const uint4* Aw = reinterpret_cast<const uint4*>(WA_g) + (size_t)w * 24 * 4 * 32 + lane;
    // GEMM1 (x_h): warp w -> mt = w&3, kslice = w>>2
    const int mt1 = w & 3, ksl1 = w >> 2;
    const uint4* Hw = reinterpret_cast<const uint4*>(HA_g) + (mt1 * 16 + ksl1 * 4) * 32 + lane;

    for (int step = 0; step < Tt; ++step) {
        // ---- P1': x_h partials via HMMA (h section of Bsm) ----
        {
            float acc[4] = {0.f, 0.f, 0.f, 0.f};
            const __half* Brow = sm.Bsm + g * BSTR + 128 + ksl1 * 64;
            #pragma unroll
            for (int i = 0; i < 4; i++) {
                uint4 Af = Hw[i * 32];
                uint32_t b0 = *(const uint32_t*)(Brow + i * 16 + tig * 2);
                uint32_t b1 = *(const uint32_t*)(Brow + i * 16 + tig * 2 + 8);
                HMMA(acc, Af, b0, b1);
            }
            float* cp = sm.zp + w * 128;   // [rowin*8 + n]
            cp[g * 8 + tig * 2]           = acc[0];
            cp[g * 8 + tig * 2 + 1]       = acc[1];
            cp[(g + 8) * 8 + tig * 2]     = acc[2];
            cp[(g + 8) * 8 + tig * 2 + 1] = acc[3];
        }
        __syncthreads();

        // ---- P3: wg0 {reduce -> x_c; z_h -> c_c -> B + impout} | wg1 {prefetch}
        if (t < 256) {
            const int j = t & 63, p = t >> 6;
            const int mt = j >> 4, rowin = j & 15;
            const float* cp = sm.zp;
            float xh[2];
            #pragma unroll
            for (int par = 0; par < 2; par++) {
                int r = 2 * p + par;
                float s = 0.f;
                #pragma unroll
                for (int ksl = 0; ksl < 4; ksl++)
                    s += cp[(ksl * 4 + mt) * 128 + rowin * 8 + r];
                xh[par] = s + sm.hist_b[j];
                float m = sm.ms[r * Dd + j], x = sm.xs[r * Dd + j];
                float xc = m * x + (1.f - m) * xh[par];
                sm.xcp[p * 128 + j * 2 + par] = xc;
                sm.xhp[p * 128 + j * 2 + par] = xh[par];
            }
            asm volatile("bar.sync 1, 256;" ::: "memory");
            u64 z = dup2(sm.fr_b[j]);
            #pragma unroll 4
            for (int k = 0; k < Dd; k++)
                z = fma2(*(const u64*)(sm.xcp + p * 128 + k * 2),
                         dup2(sm.frT[k * Dd + j]), z);
            float z0, z1; upk2(z, z0, z1);
            float2 al = *(const float2*)(sm.alp + p * 128 + j * 2);
            int r0 = 2 * p, r1 = r0 + 1;
            float m0 = sm.ms[r0 * Dd + j], m1 = sm.ms[r1 * Dd + j];
            float x0 = sm.xs[r0 * Dd + j], x1 = sm.xs[r1 * Dd + j];
            float ch0 = al.x * z0 + (1.f - al.x) * xh[0];
            float ch1 = al.y * z1 + (1.f - al.y) * xh[1];
            float cc0 = m0 * x0 + (1.f - m0) * ch0;
            float cc1 = m1 * x1 + (1.f - m1) * ch1;
            bsm_put(sm, r0, j, cc0);
            bsm_put(sm, r1, j, cc1);
            impout[(r0 + b0) * Tt * Dd + step * Dd + j] = cc0;
            impout[(r1 + b0) * Tt * Dd + step * Dd + j] = cc1;
        } else if (step + 1 < Tt) {
            const int u = t - 256;
            #pragma unroll
            for (int s = 0; s < 2; s++) {
                int e = u + s * 256;
                int r = e >> 6, jj = e & 63;
                int off = ((b0 + r) * Tt + (step + 1)) * Dd + jj;
                pf_x[s] = values[off]; pf_m[s] = masks[off];
            }
            {
                int j = u & 63, rp = u >> 6;
                pf_a0 = alpha_g[((b0 + 2 * rp)     * Tt + step + 1) * Dd + j];
                pf_a1 = alpha_g[((b0 + 2 * rp + 1) * Tt + step + 1) * Dd + j];
            }
            {
                int r = u >> 5, c0 = (u & 31) * 8;
                const float* gsrc = Gh_g + ((b0 + r) * Tt + (step + 1)) * Hh + c0;
                float4 g0 = *(const float4*)gsrc;
                float4 g1 = *(const float4*)(gsrc + 4);
                *(float4*)(sm.gh + r * Hh + c0)     = g0;
                *(float4*)(sm.gh + r * Hh + c0 + 4) = g1;
            }
        }
        __syncthreads();

        // ---- P4: HMMA GEMM z^T[1024x8] = W^T @ [cc|m|h]^T ----
        {
            float acc[4][4];
            #pragma unroll
            for (int mt = 0; mt < 4; mt++)
                #pragma unroll
                for (int q = 0; q < 4; q++) acc[mt][q] = 0.f;

            const __half* Brow = sm.Bsm + g * BSTR;
            uint4 Ab0 = Aw[0], Ab1 = Aw[32], Ab2 = Aw[64], Ab3 = Aw[96];
            #pragma unroll 2
            for (int ks = 0; ks < 24; ks++) {
                int kn = (ks + 1 < 24) ? (ks + 1) : 0;
                const uint4* Ap = Aw + kn * 128;
                uint4 An0 = Ap[0], An1 = Ap[32], An2 = Ap[64], An3 = Ap[96];
                uint32_t b0 = *(const uint32_t*)(Brow + ks * 16 + tig * 2);
                uint32_t b1 = *(const uint32_t*)(Brow + ks * 16 + tig * 2 + 8);
                HMMA(acc[0], Ab0, b0, b1);
                HMMA(acc[1], Ab1, b0, b1);
                HMMA(acc[2], Ab2, b0, b1);
                HMMA(acc[3], Ab3, b0, b1);
                Ab0 = An0; Ab1 = An1; Ab2 = An2; Ab3 = An3;
            }
            #pragma unroll
            for (int mt = 0; mt < 4; mt++) {
                int mbase = w * 64 + mt * 16 + g;
                #pragma unroll
                for (int hf = 0; hf < 2; hf++) {
                    int m = mbase + hf * 8;
                    float bias = sm.lb[m];
                    float v0 = acc[mt][hf * 2 + 0] + bias;
                    float v1 = acc[mt][hf * 2 + 1] + bias;
                    int gate = m >> 8;
                    float a0, a1;
                    if (gate == 2) { a0 = tanhfast(v0); a1 = tanhfast(v1); }
                    else           { a0 = sigf(v0);     a1 = sigf(v1);     }
                    *(float2*)(sm.zp + tig * 2048 + m * 2) = make_float2(a0, a1);
                }
            }
        }
        __syncthreads();

        // ---- P5: wg0 {c,h update + fused decay -> B fp16} | wg1 {commit} ----
        if (t < 256) {
            int r = t >> 5;
            int p = r >> 1, par = r & 1;
            int cb = (t & 31) * 8;
            bool last = (step == Tt - 1);
            float4 gA = *(const float4*)(sm.gh + r * Hh + cb);
            float4 gB = *(const float4*)(sm.gh + r * Hh + cb + 4);
            float gv8[8] = {gA.x, gA.y, gA.z, gA.w, gB.x, gB.y, gB.z, gB.w};
            #pragma unroll
            for (int cc = 0; cc < 8; cc++) {
                int c = cb + cc;
                float iv = sm.zp[p * 2048 + (0 * Hh + c) * 2 + par];
                float fv = sm.zp[p * 2048 + (1 * Hh + c) * 2 + par];
                float gg = sm.zp[p * 2048 + (2 * Hh + c) * 2 + par];
                float ov = sm.zp[p * 2048 + (3 * Hh + c) * 2 + par];
                float cold = sm.cs[r * Hh + c];
                float cnew = fv * cold + iv * gg;
                sm.cs[r * Hh + c] = cnew;
                float hh = ov * tanhfast(cnew);
                if (!last) hh *= gv8[cc];
                else sm.hp[p * 512 + c * 2 + par] = hh;
                bsm_put(sm, r, 128 + c, hh);
            }
        } else if (step + 1 < Tt) {
            const int u = t - 256;
            #pragma unroll
            for (int s = 0; s < 2; s++) {
                int e = u + s * 256;
                int r = e >> 6, jj = e & 63;
                sm.xs[e] = pf_x[s]; sm.ms[e] = pf_m[s];
                bsm_put(sm, r, 64 + jj, pf_m[s]);
            }
            int j = u & 63, rp = u >> 6;
            *(float2*)(sm.alp + rp * 128 + j * 2) = make_float2(pf_a0, pf_a1);
        }
        __syncthreads();
    }

    // ---- final: y = h @ out_W + out_b ----
    {
        int ww = t >> 5, ll = t & 31;
        if (ww < MB) {
            float s = 0.f;
            for (int k = ll; k < Hh; k += 32)
                s += sm.hp[(ww >> 1) * 512 + k * 2 + (ww & 1)] * outW[k];
            #pragma unroll
            for (int o = 16; o > 0; o >>= 1)
                s += __shfl_down_sync(0xffffffffu, s, o);
            if (ll == 0) yout[b0 + ww] = s + outB[0];
        }
    }
}

// ================================ launcher ================================

extern "C" void kernel_launch(void* const* d_in, const int* in_sizes, int n_in,
                              void* d_out, int out_size) {
    const float* values = (const float*)d_in[0];
    const float* masks  = (const float*)d_in[1];
    const float* deltas = (const float*)d_in[2];
    const float* tdhW   = (const float*)d_in[3];
    const float* tdhB   = (const float*)d_in[4];
    const float* tdxW   = (const float*)d_in[5];
    const float* tdxB   = (const float*)d_in[6];
    const float* histW  = (const float*)d_in[7];
    const float* histB  = (const float*)d_in[8];
    const float* frW    = (const float*)d_in[9];
    const float* frB    = (const float*)d_in[10];
    const float* wcW    = (const float*)d_in[11];
    const float* wcB    = (const float*)d_in[12];
    const float* lstmK  = (const float*)d_in[13];
    const float* lstmRK = (const float*)d_in[14];
    const float* lstmB  = (const float*)d_in[15];
    const float* outW   = (const float*)d_in[16];
    const float* outB   = (const float*)d_in[17];

    float* yout   = (float*)d_out;       // y_h [B,1]
    float* impout = yout + Bsz;          // imputations [B,T,D]

    transpose_kernel<<<(Hh * Dd + Dd * Dd + 255) / 256, 256>>>(tdhW, tdxW);
    int npack = 16 * 24 * 4 * 32 * 4 + 4 * 16 * 32 * 4;
    pack_wt_kernel<<<(npack + 255) / 256, 256>>>(lstmK, lstmRK, histW);
    pre_ga_kernel<<<Bsz * Tt / 8, 256>>>(deltas, masks, tdhB, tdxB, wcW, wcB);

    cudaFuncSetAttribute(rits_kernel, cudaFuncAttributeMaxDynamicSharedMemorySize,
                         (int)sizeof(Smem));
    rits_kernel<<<GRID, NT, sizeof(Smem)>>>(
        values, masks, histB, frW, frB,
        lstmB, outW, outB, yout, impout);
}